// round 9
// baseline (speedup 1.0000x reference)
#include <cuda_runtime.h>

typedef unsigned long long u64t;
typedef unsigned int u32t;

// Problem constants (fixed shapes from reference setup_inputs)
#define NB 2
#define NS 4
#define NTIME 256
#define NRECV 64
#define NPROB (NB*NS*NRECV)   // 512 independent sinkhorn problems
#define NPTS  256             // points per cloud
#define NPAIR 128             // column pairs
#define NSTEPS 24

#define LOG2E_F 1.4426950408889634f
#define LN2_F   0.6931471805599453f
#define DT_F    0.001f
#define EPSMIN_F 1e-4f        // BLUR^2
#define RATIO_F 0.25f         // SCALING^2

__device__ float g_div[NPROB];

__device__ __forceinline__ float ex2f(float x){ float y; asm("ex2.approx.ftz.f32 %0, %1;" : "=f"(y) : "f"(x)); return y; }
__device__ __forceinline__ float lg2f(float x){ float y; asm("lg2.approx.ftz.f32 %0, %1;" : "=f"(y) : "f"(x)); return y; }
// a*1.0 + c  — candidate for the rt=1 FFMA-imm form (falls back to FADD, same rounding)
__device__ __forceinline__ float fmai1(float a, float c){ float d; asm("fma.rn.f32 %0, %1, 0f3F800000, %2;" : "=f"(d) : "f"(a), "f"(c)); return d; }

__device__ __forceinline__ float lds1(u32t a){ float v; asm("ld.shared.f32 %0, [%1];" : "=f"(v) : "r"(a)); return v; }
__device__ __forceinline__ void  sts1(u32t a, float v){ asm("st.shared.f32 [%0], %1;" :: "r"(a), "f"(v)); }
__device__ __forceinline__ u32t  sptr(const void* p){ u32t a; asm("{ .reg .u64 t; cvta.to.shared.u64 t, %1; cvt.u32.u64 %0, t; }" : "=r"(a) : "l"(p)); return a; }

struct SinkSmem {
    float4 H[NPAIR];                     // (y_j, y_{j+1}, t_j, t_{j+1}) per pair
    float  xo[NPTS];                     // obs amplitudes
    float  xs[NPTS];                     // syn amplitudes
    float  F[NPTS], G[NPTS], PX[NPTS], PY[NPTS];
    float  red[32];
};

__device__ __forceinline__ float warpSum(float v){
    #pragma unroll
    for (int o = 16; o; o >>= 1) v += __shfl_xor_sync(0xffffffffu, v, o);
    return v;
}
__device__ __forceinline__ float warpMax(float v){
    #pragma unroll
    for (int o = 16; o; o >>= 1) v = fmaxf(v, __shfl_xor_sync(0xffffffffu, v, o));
    return v;
}
__device__ __forceinline__ float warpMin(float v){
    #pragma unroll
    for (int o = 16; o; o >>= 1) v = fminf(v, __shfl_xor_sync(0xffffffffu, v, o));
    return v;
}

__device__ __forceinline__ float blockSum(float v, float* red){
    v = warpSum(v);
    int w = threadIdx.x >> 5, l = threadIdx.x & 31;
    if (l == 0) red[w] = v;
    __syncthreads();
    if (w == 0) {
        float t = (l < 8) ? red[l] : 0.f;
        t = warpSum(t);
        if (l == 0) red[0] = t;
    }
    __syncthreads();
    v = red[0];
    __syncthreads();
    return v;
}
__device__ __forceinline__ float blockMax(float v, float* red){
    v = warpMax(v);
    int w = threadIdx.x >> 5, l = threadIdx.x & 31;
    if (l == 0) red[w] = v;
    __syncthreads();
    if (w == 0) {
        float t = (l < 8) ? red[l] : -3.4e38f;
        t = warpMax(t);
        if (l == 0) red[0] = t;
    }
    __syncthreads();
    v = red[0];
    __syncthreads();
    return v;
}
__device__ __forceinline__ float blockMin(float v, float* red){
    v = warpMin(v);
    int w = threadIdx.x >> 5, l = threadIdx.x & 31;
    if (l == 0) red[w] = v;
    __syncthreads();
    if (w == 0) {
        float t = (l < 8) ? red[l] : 3.4e38f;
        t = warpMin(t);
        if (l == 0) red[0] = t;
    }
    __syncthreads();
    v = red[0];
    __syncthreads();
    return v;
}

// ---- macro repetition: expand P over 0..127 with P a literal constant expr ----
#define R4(M,P)  M(P) M((P)+1) M((P)+2) M((P)+3)
#define R16(M,P) R4(M,P) R4(M,(P)+4) R4(M,(P)+8) R4(M,(P)+12)
#define R128(M)  R16(M,0) R16(M,16) R16(M,32) R16(M,48) \
                 R16(M,64) R16(M,80) R16(M,96) R16(M,112)

// 16B shared load with compile-time immediate offset
#define LDS4O(h, base, P) \
    asm("ld.shared.v4.f32 {%0,%1,%2,%3}, [%4+%5];" \
        : "=f"(h.x), "=f"(h.y), "=f"(h.z), "=f"(h.w) : "r"(base), "n"((P)*16))

// softmin over 256 columns, log2 domain, fully unrolled with immediate-J FFMAs.
// exponent(j) = la2 + pot_j*ie2 - ie2*(0.5(ti-tj)^2 + 0.5(xi-yj)^2)
//   col term t_j = la2 + pot_j*ie2 - 0.5*y_j^2*ie2 - c2*j^2   (in smem H)
//   per-pair    + xsc*y_j + u*j   (xsc = xi*ie2, u = 2*c2*i; j is an IMMEDIATE)
//   per-row consts fold back as +0.5*||X_i||^2 in the result.
__device__ __noinline__ float softmin256i(
    u32t Hb, u32t potOff, u32t ycOff,
    float xi, float ie2, float c2, float eps, float la2)
{
    const int tid = threadIdx.x;
    __syncthreads();   // previous users of H are done
    {
        float yv = lds1(ycOff + tid*4);
        float pv = lds1(potOff + tid*4);
        float jv = (float)tid;
        float tv = la2 + pv*ie2 - (0.5f*yv*yv)*ie2 - c2*jv*jv;
        u32t hb = Hb + (u32t)(tid >> 1)*16u + (u32t)(tid & 1)*4u;
        sts1(hb, yv);          // y slot
        sts1(hb + 8u, tv);     // t slot
    }
    __syncthreads();

    const float u   = 2.0f*c2*(float)tid;
    const float xsc = xi*ie2;

    // ---- pass 1: running max; J and LDS offsets are compile-time immediates ----
    float m0 = -3.0e38f, m1 = -3.0e38f, m2 = -3.0e38f, m3 = -3.0e38f;
    {
        float4 h; float b0, a0, b1, a1;
        #define P1(P) \
            LDS4O(h, Hb, P); \
            b0 = fmaf(u, (float)(2*(P)),   h.z); a0 = fmaf(xsc, h.x, b0); \
            b1 = fmaf(u, (float)(2*(P)+1), h.w); a1 = fmaf(xsc, h.y, b1); \
            m0 = fmaxf(m0, a0); m1 = fmaxf(m1, a1);
        // alternate accumulator pairs to break the FMNMX chain
        #define P1A(P) P1(P)
        R128(P1A)
        #undef P1A
        #undef P1
        (void)m2; (void)m3;
    }
    const float m = fmaxf(m0, m1);
    const float negm = -m;

    // ---- pass 2: sum of exp2(a - m) ----
    float s0 = 0.f, s1 = 0.f;
    {
        float4 h; float b0, a0, d0, e0, b1, a1, d1, e1;
        #define P2(P) \
            LDS4O(h, Hb, P); \
            b0 = fmaf(u, (float)(2*(P)),   h.z); a0 = fmaf(xsc, h.x, b0); \
            d0 = fmai1(a0, negm); e0 = ex2f(d0); s0 = fmai1(e0, s0); \
            b1 = fmaf(u, (float)(2*(P)+1), h.w); a1 = fmaf(xsc, h.y, b1); \
            d1 = fmai1(a1, negm); e1 = ex2f(d1); s1 = fmai1(e1, s1);
        R128(P2)
        #undef P2
    }
    const float s = s0 + s1;

    float ti = (float)tid * DT_F;
    return fmaf(-eps * LN2_F, m + lg2f(s), 0.5f*(ti*ti + xi*xi));
}

__global__ void __launch_bounds__(256, 4)
sink_main(const float* __restrict__ syn, const float* __restrict__ obs)
{
    __shared__ SinkSmem sm;
    const int p   = blockIdx.x;         // 0..511
    const int tid = threadIdx.x;        // row index 0..255
    const int bs  = p / NRECV;          // b*NS + s
    const int r   = p - bs * NRECV;

    const u32t Hb   = sptr(sm.H);
    const u32t xoO  = sptr(sm.xo);
    const u32t xsO  = sptr(sm.xs);
    const u32t FO   = sptr(sm.F);
    const u32t GO   = sptr(sm.G);
    const u32t PXO  = sptr(sm.PX);
    const u32t PYO  = sptr(sm.PY);

    const size_t base = (size_t)bs * NTIME * NRECV + r;
    const float xobs = obs[base + (size_t)tid * NRECV];
    const float xsyn = syn[base + (size_t)tid * NRECV];
    sm.xo[tid] = xobs;
    sm.xs[tid] = xsyn;
    sm.F[tid] = 0.f; sm.G[tid] = 0.f; sm.PX[tid] = 0.f; sm.PY[tid] = 0.f;
    __syncthreads();

    // trace mask + diameter
    float sabs_o = blockSum(fabsf(xobs), sm.red);
    float sabs_s = blockSum(fabsf(xsyn), sm.red);
    float vmax   = blockMax(fmaxf(xobs, xsyn), sm.red);
    float vmin   = blockMin(fminf(xobs, xsyn), sm.red);
    const bool masked = (sabs_o == 0.f) && (sabs_s == 0.f);

    const float trange   = (float)(NTIME - 1) * DT_F;
    const float diameter = fmaxf(trange, vmax - vmin);
    const float eps0     = diameter * diameter;           // P = 2
    const float la2      = -lg2f((float)NPTS);

    float fi = 0.f, gi = 0.f, pxi = 0.f, pyi = 0.f;
    float eps_raw = eps0;

    for (int k = 0; k < NSTEPS; k++) {
        const float eps = fmaxf(eps_raw, EPSMIN_F);
        eps_raw *= RATIO_F;
        const float ie2 = LOG2E_F / eps;
        const float c2  = 0.5f * DT_F * DT_F * ie2;

        // all four softmins read OLD potentials (scan-step semantics)
        fi  = softmin256i(Hb, GO,  xsO, xobs, ie2, c2, eps, la2);
        gi  = softmin256i(Hb, FO,  xoO, xsyn, ie2, c2, eps, la2);
        pxi = 0.5f * (pxi + softmin256i(Hb, PXO, xoO, xobs, ie2, c2, eps, la2));
        pyi = 0.5f * (pyi + softmin256i(Hb, PYO, xsO, xsyn, ie2, c2, eps, la2));

        __syncthreads();   // everyone done reading old potentials
        sm.F[tid] = fi; sm.G[tid] = gi; sm.PX[tid] = pxi; sm.PY[tid] = pyi;
    }
    __syncthreads();

    // S = sum w*(f - px) + sum w*(g - py), w = 1/n
    float contrib = (fi - pxi + gi - pyi) * (1.0f / (float)NPTS);
    float div = blockSum(contrib, sm.red);
    if (tid == 0) g_div[p] = masked ? 0.f : div;
}

// Deterministic final reduction: one block per batch, 256 problems each.
__global__ void __launch_bounds__(256)
sink_finalize(float* __restrict__ out)
{
    __shared__ float red[32];
    const int b = blockIdx.x;
    float v = g_div[b * (NS * NRECV) + threadIdx.x];
    v = blockSum(v, red);
    if (threadIdx.x == 0) out[b] = v;
}

extern "C" void kernel_launch(void* const* d_in, const int* in_sizes, int n_in,
                              void* d_out, int out_size)
{
    const float* syn = (const float*)d_in[0];   // syn_data [B,S,NT,NR]
    const float* obs = (const float*)d_in[1];   // obs_data [B,S,NT,NR]
    float* out = (float*)d_out;                 // [B] float32

    sink_main<<<NPROB, 256>>>(syn, obs);
    sink_finalize<<<NB, 256>>>(out);
}

// round 10
// speedup vs baseline: 4.6841x; 4.6841x over previous
#include <cuda_runtime.h>

typedef unsigned int u32t;

// Problem constants (fixed shapes from reference setup_inputs)
#define NB 2
#define NS 4
#define NTIME 256
#define NRECV 64
#define NPROB (NB*NS*NRECV)   // 512 independent sinkhorn problems
#define NPTS  256             // points per cloud
#define NSTEPS 24

#define LOG2E_F 1.4426950408889634f
#define LN2_F   0.6931471805599453f
#define DT_F    0.001f
#define EPSMIN_F 1e-4f        // BLUR^2
#define RATIO_F 0.25f         // SCALING^2

__device__ float g_div[NPROB];

__device__ __forceinline__ float ex2f(float x){ float y; asm("ex2.approx.ftz.f32 %0, %1;" : "=f"(y) : "f"(x)); return y; }
__device__ __forceinline__ float lg2f(float x){ float y; asm("lg2.approx.ftz.f32 %0, %1;" : "=f"(y) : "f"(x)); return y; }
// a*1.0 + c : candidate for the rt=1 FFMA-imm form (same rounding as FADD either way)
__device__ __forceinline__ float fmai1(float a, float c){ float d; asm("fma.rn.f32 %0, %1, 0f3F800000, %2;" : "=f"(d) : "f"(a), "f"(c)); return d; }

struct SinkSmem {
    float4 H[NPTS];    // per column j: (y_j, tt_j = j*DT, T_j, 0)
    float  xo[NPTS];   // obs amplitudes
    float  xs[NPTS];   // syn amplitudes
    float  F[NPTS], G[NPTS], PX[NPTS], PY[NPTS];
    float  red[32];
};

__device__ __forceinline__ float warpSum(float v){
    #pragma unroll
    for (int o = 16; o; o >>= 1) v += __shfl_xor_sync(0xffffffffu, v, o);
    return v;
}
__device__ __forceinline__ float warpMax(float v){
    #pragma unroll
    for (int o = 16; o; o >>= 1) v = fmaxf(v, __shfl_xor_sync(0xffffffffu, v, o));
    return v;
}
__device__ __forceinline__ float warpMin(float v){
    #pragma unroll
    for (int o = 16; o; o >>= 1) v = fminf(v, __shfl_xor_sync(0xffffffffu, v, o));
    return v;
}

__device__ __forceinline__ float blockSum(float v, float* red){
    v = warpSum(v);
    int w = threadIdx.x >> 5, l = threadIdx.x & 31;
    if (l == 0) red[w] = v;
    __syncthreads();
    if (w == 0) {
        float t = (l < 8) ? red[l] : 0.f;
        t = warpSum(t);
        if (l == 0) red[0] = t;
    }
    __syncthreads();
    v = red[0];
    __syncthreads();
    return v;
}
__device__ __forceinline__ float blockMax(float v, float* red){
    v = warpMax(v);
    int w = threadIdx.x >> 5, l = threadIdx.x & 31;
    if (l == 0) red[w] = v;
    __syncthreads();
    if (w == 0) {
        float t = (l < 8) ? red[l] : -3.4e38f;
        t = warpMax(t);
        if (l == 0) red[0] = t;
    }
    __syncthreads();
    v = red[0];
    __syncthreads();
    return v;
}
__device__ __forceinline__ float blockMin(float v, float* red){
    v = warpMin(v);
    int w = threadIdx.x >> 5, l = threadIdx.x & 31;
    if (l == 0) red[w] = v;
    __syncthreads();
    if (w == 0) {
        float t = (l < 8) ? red[l] : 3.4e38f;
        t = warpMin(t);
        if (l == 0) red[0] = t;
    }
    __syncthreads();
    v = red[0];
    __syncthreads();
    return v;
}

// softmin over 256 columns, log2 domain.
// A_ij = la2 + pot_j*ie2 - ie2*[0.5(t_i-t_j)^2 + 0.5(x_i-y_j)^2]
//      = T_j + tsc*tt_j + xsc*y_j + C_i,   with
//   T_j  = la2 + pot_j*ie2 - 0.5*ie2*(tt_j^2 + y_j^2)     (shared, per column)
//   tsc  = ie2*t_i,  xsc = ie2*x_i                         (per row)
//   C_i  = -0.5*ie2*(t_i^2 + x_i^2)  -> folds back as +0.5*(t_i^2+x_i^2)
// result = -eps*ln2*(m + log2 s) + 0.5*(t_i^2 + x_i^2)
__device__ __forceinline__ float softmin256(
    const float* __restrict__ pot, const float* __restrict__ yc,
    SinkSmem& sm,
    float xi, float ie2, float eps, float la2)
{
    const int tid = threadIdx.x;
    __syncthreads();   // previous users of H are done
    {
        float yv = yc[tid];
        float tt = (float)tid * DT_F;
        float Tv = la2 + pot[tid]*ie2 - 0.5f*ie2*(tt*tt + yv*yv);
        sm.H[tid] = make_float4(yv, tt, Tv, 0.f);
    }
    __syncthreads();

    const float ti  = (float)tid * DT_F;
    const float tsc = ti * ie2;
    const float xsc = xi * ie2;
    const float4* __restrict__ H = sm.H;

    // ---- pass 1: running max (FMNMX rides the alu pipe) ----
    float m0 = -3.0e38f, m1 = -3.0e38f;
    #pragma unroll 1
    for (int j0 = 0; j0 < NPTS; j0 += 8) {
        #pragma unroll
        for (int k = 0; k < 8; k += 2) {
            float4 ha = H[j0 + k];
            float4 hb = H[j0 + k + 1];
            float aa = fmaf(xsc, ha.x, fmaf(tsc, ha.y, ha.z));
            float ab = fmaf(xsc, hb.x, fmaf(tsc, hb.y, hb.z));
            m0 = fmaxf(m0, aa);
            m1 = fmaxf(m1, ab);
        }
    }
    const float m = fmaxf(m0, m1);
    const float negm = -m;

    // ---- pass 2: sum of exp2(A - m) ----
    float s0 = 0.f, s1 = 0.f;
    #pragma unroll 1
    for (int j0 = 0; j0 < NPTS; j0 += 8) {
        #pragma unroll
        for (int k = 0; k < 8; k += 2) {
            float4 ha = H[j0 + k];
            float4 hb = H[j0 + k + 1];
            float aa = fmaf(xsc, ha.x, fmaf(tsc, ha.y, ha.z));
            float ab = fmaf(xsc, hb.x, fmaf(tsc, hb.y, hb.z));
            float ea = ex2f(fmai1(aa, negm));
            float eb = ex2f(fmai1(ab, negm));
            s0 = fmai1(ea, s0);
            s1 = fmai1(eb, s1);
        }
    }
    const float s = s0 + s1;

    return fmaf(-eps * LN2_F, m + lg2f(s), 0.5f*(ti*ti + xi*xi));
}

__global__ void __launch_bounds__(256, 4)
sink_main(const float* __restrict__ syn, const float* __restrict__ obs)
{
    __shared__ SinkSmem sm;
    const int p   = blockIdx.x;         // 0..511
    const int tid = threadIdx.x;        // row index 0..255
    const int bs  = p / NRECV;          // b*NS + s
    const int r   = p - bs * NRECV;

    const size_t base = (size_t)bs * NTIME * NRECV + r;
    const float xobs = obs[base + (size_t)tid * NRECV];
    const float xsyn = syn[base + (size_t)tid * NRECV];
    sm.xo[tid] = xobs;
    sm.xs[tid] = xsyn;
    sm.F[tid] = 0.f; sm.G[tid] = 0.f; sm.PX[tid] = 0.f; sm.PY[tid] = 0.f;
    __syncthreads();

    // trace mask + diameter
    float sabs_o = blockSum(fabsf(xobs), sm.red);
    float sabs_s = blockSum(fabsf(xsyn), sm.red);
    float vmax   = blockMax(fmaxf(xobs, xsyn), sm.red);
    float vmin   = blockMin(fminf(xobs, xsyn), sm.red);
    const bool masked = (sabs_o == 0.f) && (sabs_s == 0.f);

    const float trange   = (float)(NTIME - 1) * DT_F;
    const float diameter = fmaxf(trange, vmax - vmin);
    const float eps0     = diameter * diameter;           // P = 2
    const float la2      = -lg2f((float)NPTS);

    float fi = 0.f, gi = 0.f, pxi = 0.f, pyi = 0.f;
    float eps_raw = eps0;

    for (int k = 0; k < NSTEPS; k++) {
        const float eps = fmaxf(eps_raw, EPSMIN_F);
        eps_raw *= RATIO_F;
        const float ie2 = LOG2E_F / eps;

        // all four softmins read OLD potentials (scan-step semantics)
        fi  = softmin256(sm.G,  sm.xs, sm, xobs, ie2, eps, la2);
        gi  = softmin256(sm.F,  sm.xo, sm, xsyn, ie2, eps, la2);
        pxi = 0.5f * (pxi + softmin256(sm.PX, sm.xo, sm, xobs, ie2, eps, la2));
        pyi = 0.5f * (pyi + softmin256(sm.PY, sm.xs, sm, xsyn, ie2, eps, la2));

        __syncthreads();   // everyone done reading old potentials
        sm.F[tid] = fi; sm.G[tid] = gi; sm.PX[tid] = pxi; sm.PY[tid] = pyi;
    }
    __syncthreads();

    // S = sum w*(f - px) + sum w*(g - py), w = 1/n
    float contrib = (fi - pxi + gi - pyi) * (1.0f / (float)NPTS);
    float div = blockSum(contrib, sm.red);
    if (tid == 0) g_div[p] = masked ? 0.f : div;
}

// Deterministic final reduction: one block per batch, 256 problems each.
__global__ void __launch_bounds__(256)
sink_finalize(float* __restrict__ out)
{
    __shared__ float red[32];
    const int b = blockIdx.x;
    float v = g_div[b * (NS * NRECV) + threadIdx.x];
    v = blockSum(v, red);
    if (threadIdx.x == 0) out[b] = v;
}

extern "C" void kernel_launch(void* const* d_in, const int* in_sizes, int n_in,
                              void* d_out, int out_size)
{
    const float* syn = (const float*)d_in[0];   // syn_data [B,S,NT,NR]
    const float* obs = (const float*)d_in[1];   // obs_data [B,S,NT,NR]
    float* out = (float*)d_out;                 // [B] float32

    sink_main<<<NPROB, 256>>>(syn, obs);
    sink_finalize<<<NB, 2 * 128>>>(out);
}

// round 11
// speedup vs baseline: 5.9003x; 1.2596x over previous
#include <cuda_runtime.h>

// Problem constants (fixed shapes from reference setup_inputs)
#define NB 2
#define NS 4
#define NTIME 256
#define NRECV 64
#define NPROB (NB*NS*NRECV)   // 512 independent sinkhorn problems
#define NPTS  256             // points per cloud
#define NSTEPS 24

#define LOG2E_F 1.4426950408889634f
#define LN2_F   0.6931471805599453f
#define DT_F    0.001f
#define EPSMIN_F 1e-4f        // BLUR^2
#define RATIO_F 0.25f         // SCALING^2

__device__ float g_div[NPROB];          // per-problem divergence
__device__ unsigned int g_done = 0;     // last-block ticket (reset every launch)

__device__ __forceinline__ float ex2f(float x){ float y; asm("ex2.approx.ftz.f32 %0, %1;" : "=f"(y) : "f"(x)); return y; }
__device__ __forceinline__ float lg2f(float x){ float y; asm("lg2.approx.ftz.f32 %0, %1;" : "=f"(y) : "f"(x)); return y; }
// a*1.0 + c : FFMA with immediate multiplier (rt=1 form); rounding identical to FADD
__device__ __forceinline__ float fmai1(float a, float c){ float d; asm("fma.rn.f32 %0, %1, 0f3F800000, %2;" : "=f"(d) : "f"(a), "f"(c)); return d; }

struct SinkSmem {
    float2 hp[NPTS];   // (y_j, T_j) per column
    float  xo[NPTS];   // obs amplitudes
    float  xs[NPTS];   // syn amplitudes
    float  F[NPTS], G[NPTS], PX[NPTS], PY[NPTS];
    float  red[32];
};

__device__ __forceinline__ float warpSum(float v){
    #pragma unroll
    for (int o = 16; o; o >>= 1) v += __shfl_xor_sync(0xffffffffu, v, o);
    return v;
}
__device__ __forceinline__ float warpMax(float v){
    #pragma unroll
    for (int o = 16; o; o >>= 1) v = fmaxf(v, __shfl_xor_sync(0xffffffffu, v, o));
    return v;
}
__device__ __forceinline__ float warpMin(float v){
    #pragma unroll
    for (int o = 16; o; o >>= 1) v = fminf(v, __shfl_xor_sync(0xffffffffu, v, o));
    return v;
}

__device__ __forceinline__ float blockSum(float v, float* red){
    v = warpSum(v);
    int w = threadIdx.x >> 5, l = threadIdx.x & 31;
    if (l == 0) red[w] = v;
    __syncthreads();
    if (w == 0) {
        float t = (l < 8) ? red[l] : 0.f;
        t = warpSum(t);
        if (l == 0) red[0] = t;
    }
    __syncthreads();
    v = red[0];
    __syncthreads();
    return v;
}
__device__ __forceinline__ float blockMax(float v, float* red){
    v = warpMax(v);
    int w = threadIdx.x >> 5, l = threadIdx.x & 31;
    if (l == 0) red[w] = v;
    __syncthreads();
    if (w == 0) {
        float t = (l < 8) ? red[l] : -3.4e38f;
        t = warpMax(t);
        if (l == 0) red[0] = t;
    }
    __syncthreads();
    v = red[0];
    __syncthreads();
    return v;
}
__device__ __forceinline__ float blockMin(float v, float* red){
    v = warpMin(v);
    int w = threadIdx.x >> 5, l = threadIdx.x & 31;
    if (l == 0) red[w] = v;
    __syncthreads();
    if (w == 0) {
        float t = (l < 8) ? red[l] : 3.4e38f;
        t = warpMin(t);
        if (l == 0) red[0] = t;
    }
    __syncthreads();
    v = red[0];
    __syncthreads();
    return v;
}

// softmin over 256 columns, log2 domain (R1-validated structure):
// exponent(j) = la2 + pot_j*ie2 - ie2*(0.5(ti-tj)^2 + 0.5(xi-yj)^2)
//   col term T_j = la2 + pot_j*ie2 - 0.5*y_j^2*ie2 - c2*j^2   (smem, float2 with y_j)
//   per-pair    + xsc*y_j + u*jf   (xsc = xi*ie2, u = 2*c2*i; jf register counter)
//   per-row consts fold back as +0.5*||X_i||^2 in the result.
__device__ __forceinline__ float softmin256(
    const float* __restrict__ pot, const float* __restrict__ yc,
    SinkSmem& sm,
    float xi, float ie2, float c2, float eps, float la2)
{
    const int tid = threadIdx.x;
    __syncthreads();  // previous users of hp are done
    {
        float yv = yc[tid];
        float jv = (float)tid;
        float t  = la2 + pot[tid]*ie2 - (0.5f*yv*yv)*ie2 - c2*jv*jv;
        sm.hp[tid] = make_float2(yv, t);
    }
    __syncthreads();

    const float xsc = xi * ie2;
    const float u   = 2.0f * c2 * (float)tid;

    // pass 1: max
    float m = -3.4e38f;
    float jf = 0.f;
    #pragma unroll 8
    for (int j = 0; j < NPTS; j++) {
        float2 h = sm.hp[j];
        float a = fmaf(xsc, h.x, h.y);
        a = fmaf(u, jf, a);
        m = fmaxf(m, a);
        jf += 1.f;
    }
    const float negm = -m;

    // pass 2: sum of exp2 (subtract & accumulate via rt=1 FFMA-imm forms)
    float s0 = 0.f, s1 = 0.f;
    jf = 0.f;
    #pragma unroll 8
    for (int j = 0; j < NPTS; j += 2) {
        float2 ha = sm.hp[j];
        float2 hb = sm.hp[j+1];
        float aa = fmaf(xsc, ha.x, ha.y);
        aa = fmaf(u, jf, aa);
        float ab = fmaf(xsc, hb.x, hb.y);
        ab = fmaf(u, jf + 1.f, ab);
        float ea = ex2f(fmai1(aa, negm));
        float eb = ex2f(fmai1(ab, negm));
        s0 = fmai1(ea, s0);
        s1 = fmai1(eb, s1);
        jf += 2.f;
    }
    const float s = s0 + s1;

    float ti = (float)tid * DT_F;
    return fmaf(-eps * LN2_F, m + lg2f(s), 0.5f * (ti*ti + xi*xi));
}

__global__ void __launch_bounds__(256, 4)
sink_main(const float* __restrict__ syn, const float* __restrict__ obs,
          float* __restrict__ out)
{
    __shared__ SinkSmem sm;
    __shared__ bool sLast;
    const int p   = blockIdx.x;         // 0..511
    const int tid = threadIdx.x;        // row index 0..255
    const int bs  = p / NRECV;          // b*NS + s
    const int r   = p - bs * NRECV;

    const size_t base = (size_t)bs * NTIME * NRECV + r;
    const float xobs = obs[base + (size_t)tid * NRECV];
    const float xsyn = syn[base + (size_t)tid * NRECV];
    sm.xo[tid] = xobs;
    sm.xs[tid] = xsyn;
    sm.F[tid] = 0.f; sm.G[tid] = 0.f; sm.PX[tid] = 0.f; sm.PY[tid] = 0.f;
    __syncthreads();

    // trace mask + diameter
    float sabs_o = blockSum(fabsf(xobs), sm.red);
    float sabs_s = blockSum(fabsf(xsyn), sm.red);
    float vmax   = blockMax(fmaxf(xobs, xsyn), sm.red);
    float vmin   = blockMin(fminf(xobs, xsyn), sm.red);
    const bool masked = (sabs_o == 0.f) && (sabs_s == 0.f);

    const float trange   = (float)(NTIME - 1) * DT_F;
    const float diameter = fmaxf(trange, vmax - vmin);
    const float eps0     = diameter * diameter;           // P = 2
    const float la2      = -lg2f((float)NPTS);

    float fi = 0.f, gi = 0.f, pxi = 0.f, pyi = 0.f;
    float eps_raw = eps0;

    for (int k = 0; k < NSTEPS; k++) {
        const float eps = fmaxf(eps_raw, EPSMIN_F);
        eps_raw *= RATIO_F;
        const float ie2 = LOG2E_F / eps;
        const float c2  = 0.5f * DT_F * DT_F * ie2;

        // all four softmins read OLD potentials (scan-step semantics)
        fi  = softmin256(sm.G,  sm.xs, sm, xobs, ie2, c2, eps, la2);
        gi  = softmin256(sm.F,  sm.xo, sm, xsyn, ie2, c2, eps, la2);
        pxi = 0.5f * (pxi + softmin256(sm.PX, sm.xo, sm, xobs, ie2, c2, eps, la2));
        pyi = 0.5f * (pyi + softmin256(sm.PY, sm.xs, sm, xsyn, ie2, c2, eps, la2));

        __syncthreads();   // everyone done reading old potentials
        sm.F[tid] = fi; sm.G[tid] = gi; sm.PX[tid] = pxi; sm.PY[tid] = pyi;
    }
    __syncthreads();

    // S = sum w*(f - px) + sum w*(g - py), w = 1/n
    float contrib = (fi - pxi + gi - pyi) * (1.0f / (float)NPTS);
    float div = blockSum(contrib, sm.red);

    // ---- fused finalize: last-arriving block reduces g_div deterministically ----
    if (tid == 0) {
        g_div[p] = masked ? 0.f : div;
        __threadfence();
        unsigned int t = atomicAdd(&g_done, 1u);
        sLast = (t == NPROB - 1u);
    }
    __syncthreads();

    if (sLast) {
        // all 512 g_div writes are visible (their fences precede our winning ticket)
        const int perB = NS * NRECV;   // 256
        float v0 = g_div[tid];                 // batch 0
        float v1 = g_div[perB + tid];          // batch 1
        float o0 = blockSum(v0, sm.red);
        float o1 = blockSum(v1, sm.red);
        if (tid == 0) {
            out[0] = o0;
            out[1] = o1;
            g_done = 0;                        // reset ticket for next launch
        }
    }
}

extern "C" void kernel_launch(void* const* d_in, const int* in_sizes, int n_in,
                              void* d_out, int out_size)
{
    const float* syn = (const float*)d_in[0];   // syn_data [B,S,NT,NR]
    const float* obs = (const float*)d_in[1];   // obs_data [B,S,NT,NR]
    float* out = (float*)d_out;                 // [B] float32

    sink_main<<<NPROB, 256>>>(syn, obs, out);
}